// round 9
// baseline (speedup 1.0000x reference)
#include <cuda_runtime.h>
#include <cuda_bf16.h>
#include <cstdint>

#define B_   64
#define T_   4096
#define DIM_ 256
#define NF_  32
#define KS_  31
#define PAD_ 15
#define NEG_ (-1e30f)
#define BT_  (B_ * T_)

// ---------------- scratch (device globals; no allocations) ----------------
__device__ float g_q[B_ * DIM_];                 // 64 KB
__device__ float g_F[(size_t)BT_ * NF_];         // 32 MB
__device__ float g_S[BT_];                       // 1 MB raw masked scores
__device__ unsigned char g_mask[BT_];            // 256 KB normalized mask
__device__ float g_partial[4 * B_ * DIM_];       // 256 KB context partials
__device__ float g_align_scratch[BT_];           // fallback align storage
__device__ float g_att_scratch[B_ * DIM_];       // fallback attention storage
__device__ int   g_det[2];                       // [0]=u8 evidence, [1]=f32 evidence

// ---------------- helpers ----------------
__device__ __forceinline__ unsigned long long pk2(float lo, float hi) {
    unsigned long long r;
    asm("mov.b64 %0, {%1, %2};" : "=l"(r) : "f"(lo), "f"(hi));
    return r;
}
__device__ __forceinline__ float2 upk2(unsigned long long v) {
    float2 r;
    asm("mov.b64 {%0, %1}, %2;" : "=f"(r.x), "=f"(r.y) : "l"(v));
    return r;
}
__device__ __forceinline__ unsigned long long fma2(unsigned long long a,
                                                   unsigned long long b,
                                                   unsigned long long c) {
    unsigned long long d;
    asm("fma.rn.f32x2 %0, %1, %2, %3;" : "=l"(d) : "l"(a), "l"(b), "l"(c));
    return d;
}
// tanh(x) = 1 - 2/(exp(2x)+1); 2 MUFU ops, abs err ~1e-7
__device__ __forceinline__ float fast_tanh(float x) {
    float e = __expf(2.0f * x);
    return 1.0f - __fdividef(2.0f, e + 1.0f);
}

// ---------------- K0: mask dtype detection + normalization ----------------
__global__ void k_reset() { g_det[0] = 0; g_det[1] = 0; }

// sample only the first 65536 words (valid for every candidate dtype)
__global__ void k_detect(const unsigned int* __restrict__ mw) {
    int i = (blockIdx.x * 256 + threadIdx.x) * 4;
#pragma unroll
    for (int j = 0; j < 4; ++j) {
        unsigned v = mw[i + j];
        if (v == 0x3f800000u)      atomicOr(&g_det[1], 1);   // float 1.0
        else if (v > 1u)           atomicOr(&g_det[0], 1);   // packed bytes
    }
}

__global__ void k_mconv(const void* __restrict__ m) {
    int i = blockIdx.x * 256 + threadIdx.x;
    if (i >= BT_) return;
    int isf32 = g_det[1], isu8 = g_det[0];
    unsigned char r;
    if (isf32)      r = (((const float*)m)[i] != 0.0f);
    else if (isu8)  r = (((const unsigned char*)m)[i] != 0);
    else            r = (((const int*)m)[i] != 0);
    g_mask[i] = r;
}

// ---------------- K1: q = query @ Wq^T ----------------
__global__ void k_qproj(const float* __restrict__ query, const float* __restrict__ Wq) {
    __shared__ float qs[DIM_];
    int b = blockIdx.x, d = threadIdx.x;
    qs[d] = query[b * DIM_ + d];
    __syncthreads();
    const float* wr = Wq + (size_t)d * DIM_;
    float a = 0.0f;
#pragma unroll 8
    for (int e = 0; e < DIM_; ++e) a = fmaf(qs[e], wr[e], a);
    g_q[b * DIM_ + d] = a;
}

// ---------------- K2: F[b,t,f] = conv(prev_alignment) ----------------
__global__ void k_conv(const float* __restrict__ pa, const float* __restrict__ cw) {
    __shared__ float pa_sh[128 + KS_ - 1];   // 158
    __shared__ float cw_sh[NF_ * KS_];       // [f][k]
    int b = blockIdx.y, t0 = blockIdx.x * 128;
    int tid = threadIdx.x;
    for (int i = tid; i < 128 + KS_ - 1; i += 256) {
        int t = t0 + i - PAD_;
        pa_sh[i] = (t >= 0 && t < T_) ? pa[b * T_ + t] : 0.0f;
    }
    for (int i = tid; i < NF_ * KS_; i += 256) cw_sh[i] = cw[i];
    __syncthreads();
    int f = tid & 31, g = tid >> 5;
#pragma unroll
    for (int i = 0; i < 16; ++i) {
        int tl = g * 16 + i;
        float a = 0.0f;
#pragma unroll
        for (int k = 0; k < KS_; ++k)
            a = fmaf(pa_sh[tl + k], cw_sh[f * KS_ + k], a);
        g_F[((size_t)(b * T_ + t0 + tl)) * NF_ + f] = a;
    }
}

// ---------------- K3: scores (the hot kernel) ----------------
#define PITCH 264   // 32 rows * 264 floats, 16B-aligned rows, conflict-free v4 reads

__global__ void __launch_bounds__(256, 2)
k_score(const float* __restrict__ keys, const float* __restrict__ Wloc,
        const float* __restrict__ vw, const float* __restrict__ vb) {
    __shared__ float WlocT[NF_ * PITCH];   // [f][d], 33792 B
    __shared__ float Fsh[8][NF_][8];       // [warp][f][tt], 8192 B

    const int b = blockIdx.y;
    const int t_base = blockIdx.x * 512;
    const int tid = threadIdx.x;
    const int wid = tid >> 5;
    const int lane = tid & 31;

    // stage Wloc transposed: WlocT[f][d] = Wloc[d][f]   (coalesced global reads)
    for (int idx = tid; idx < DIM_ * NF_; idx += 256) {
        int f = idx & 31, d = idx >> 5;
        WlocT[f * PITCH + d] = Wloc[d * NF_ + f];
    }
    __syncthreads();

    // per-lane constants: d-groups {4*lane..4*lane+3} and {128+4*lane..}
    const float4 q0  = *(const float4*)&g_q[b * DIM_ + lane * 4];
    const float4 q1  = *(const float4*)&g_q[b * DIM_ + 128 + lane * 4];
    const float4 vw0 = *(const float4*)&vw[lane * 4];
    const float4 vw1 = *(const float4*)&vw[128 + lane * 4];
    const float vb0 = vb[0];

    for (int iter = 0; iter < 8; ++iter) {
        const int t0 = t_base + iter * 64 + wid * 8;

        // load F for 8 t's (lane <-> filter index), stage to Fsh[wid][lane][tt]
        float Fv[8];
#pragma unroll
        for (int tt = 0; tt < 8; ++tt)
            Fv[tt] = g_F[((size_t)(b * T_ + t0 + tt)) * NF_ + lane];
        __syncwarp();
        *(float4*)&Fsh[wid][lane][0] = make_float4(Fv[0], Fv[1], Fv[2], Fv[3]);
        *(float4*)&Fsh[wid][lane][4] = make_float4(Fv[4], Fv[5], Fv[6], Fv[7]);
        __syncwarp();

        // loc accumulators: acc[tt][p], p=0..3 -> f32x2 pairs covering 8 d's
        unsigned long long acc[8][4];
#pragma unroll
        for (int tt = 0; tt < 8; ++tt)
#pragma unroll
            for (int p = 0; p < 4; ++p) acc[tt][p] = 0ull;

#pragma unroll 8
        for (int f = 0; f < NF_; ++f) {
            const float4 wa = *(const float4*)&WlocT[f * PITCH + lane * 4];
            const float4 wb = *(const float4*)&WlocT[f * PITCH + 128 + lane * 4];
            const unsigned long long w0 = pk2(wa.x, wa.y);
            const unsigned long long w1 = pk2(wa.z, wa.w);
            const unsigned long long w2 = pk2(wb.x, wb.y);
            const unsigned long long w3 = pk2(wb.z, wb.w);
            const float4 Fa = *(const float4*)&Fsh[wid][f][0];   // broadcast LDS.128
            const float4 Fb = *(const float4*)&Fsh[wid][f][4];
            const float Ft[8] = {Fa.x, Fa.y, Fa.z, Fa.w, Fb.x, Fb.y, Fb.z, Fb.w};
#pragma unroll
            for (int tt = 0; tt < 8; ++tt) {
                const unsigned long long Fp = pk2(Ft[tt], Ft[tt]);
                acc[tt][0] = fma2(Fp, w0, acc[tt][0]);
                acc[tt][1] = fma2(Fp, w1, acc[tt][1]);
                acc[tt][2] = fma2(Fp, w2, acc[tt][2]);
                acc[tt][3] = fma2(Fp, w3, acc[tt][3]);
            }
        }

        // tail: add keys + q, tanh, dot with v_w, warp-reduce, write score
#pragma unroll
        for (int tt = 0; tt < 8; ++tt) {
            const int t = t0 + tt;
            const float4 k0 = *(const float4*)&keys[((size_t)(b * T_ + t)) * DIM_ + lane * 4];
            const float4 k1 = *(const float4*)&keys[((size_t)(b * T_ + t)) * DIM_ + 128 + lane * 4];
            const float2 l0 = upk2(acc[tt][0]);
            const float2 l1 = upk2(acc[tt][1]);
            const float2 l2 = upk2(acc[tt][2]);
            const float2 l3 = upk2(acc[tt][3]);
            float s;
            s  = vw0.x * fast_tanh(q0.x + k0.x + l0.x);
            s += vw0.y * fast_tanh(q0.y + k0.y + l0.y);
            s += vw0.z * fast_tanh(q0.z + k0.z + l1.x);
            s += vw0.w * fast_tanh(q0.w + k0.w + l1.y);
            s += vw1.x * fast_tanh(q1.x + k1.x + l2.x);
            s += vw1.y * fast_tanh(q1.y + k1.y + l2.y);
            s += vw1.z * fast_tanh(q1.z + k1.z + l3.x);
            s += vw1.w * fast_tanh(q1.w + k1.w + l3.y);
#pragma unroll
            for (int o = 16; o > 0; o >>= 1)
                s += __shfl_xor_sync(0xffffffffu, s, o);
            if (lane == 0) {
                s += vb0;
                if (g_mask[b * T_ + t]) s = NEG_;
                g_S[b * T_ + t] = s;
            }
        }
    }
}

// ---------------- K4: softmax per row ----------------
__global__ void k_softmax(float* __restrict__ align_out) {
    const int b = blockIdx.x, tid = threadIdx.x;   // 512 threads
    __shared__ float sha[16], shb[16];
    float v[8];
    float mx = -3.4e38f;
#pragma unroll
    for (int i = 0; i < 8; ++i) {
        v[i] = g_S[b * T_ + tid + i * 512];
        mx = fmaxf(mx, v[i]);
    }
#pragma unroll
    for (int o = 16; o > 0; o >>= 1) mx = fmaxf(mx, __shfl_xor_sync(0xffffffffu, mx, o));
    if ((tid & 31) == 0) sha[tid >> 5] = mx;
    __syncthreads();
    if (tid < 32) {
        float t = (tid < 16) ? sha[tid] : -3.4e38f;
#pragma unroll
        for (int o = 8; o > 0; o >>= 1) t = fmaxf(t, __shfl_xor_sync(0xffffffffu, t, o));
        if (tid == 0) sha[0] = t;
    }
    __syncthreads();
    mx = sha[0];
    float sum = 0.0f;
#pragma unroll
    for (int i = 0; i < 8; ++i) { v[i] = __expf(v[i] - mx); sum += v[i]; }
#pragma unroll
    for (int o = 16; o > 0; o >>= 1) sum += __shfl_xor_sync(0xffffffffu, sum, o);
    if ((tid & 31) == 0) shb[tid >> 5] = sum;
    __syncthreads();
    if (tid < 32) {
        float t = (tid < 16) ? shb[tid] : 0.0f;
#pragma unroll
        for (int o = 8; o > 0; o >>= 1) t += __shfl_xor_sync(0xffffffffu, t, o);
        if (tid == 0) shb[0] = t;
    }
    __syncthreads();
    const float inv = 1.0f / shb[0];
#pragma unroll
    for (int i = 0; i < 8; ++i)
        align_out[b * T_ + tid + i * 512] = v[i] * inv;
}

// ---------------- K5: context partials + K6: reduce ----------------
__global__ void k_context(const float* __restrict__ values, const float* __restrict__ align) {
    __shared__ float al[1024];
    const int b = blockIdx.y, sp = blockIdx.x;
    const int tid = threadIdx.x;
    const int tbase = sp * 1024;
    for (int i = tid; i < 1024; i += 256) al[i] = align[b * T_ + tbase + i];
    __syncthreads();
    const float* vp = values + ((size_t)(b * T_ + tbase)) * DIM_ + tid;
    float acc = 0.0f;
#pragma unroll 8
    for (int t = 0; t < 1024; ++t)
        acc = fmaf(al[t], vp[(size_t)t * DIM_], acc);
    g_partial[(sp * B_ + b) * DIM_ + tid] = acc;
}

__global__ void k_reduce(float* __restrict__ att_out) {
    const int b = blockIdx.x, d = threadIdx.x;
    float s = 0.0f;
#pragma unroll
    for (int sp = 0; sp < 4; ++sp) s += g_partial[(sp * B_ + b) * DIM_ + d];
    att_out[b * DIM_ + d] = s;
}

// ---------------- launch ----------------
extern "C" void kernel_launch(void* const* d_in, const int* in_sizes, int n_in,
                              void* d_out, int out_size) {
    const float* query = (const float*)d_in[0];
    const float* keys  = (const float*)d_in[1];
    const float* values = (const float*)d_in[2];
    const float* pa    = (const float*)d_in[3];
    const void*  mask  = d_in[4];
    const float* Wq    = (const float*)d_in[5];
    const float* cw    = (const float*)d_in[6];
    const float* Wloc  = (const float*)d_in[7];
    const float* vw    = (const float*)d_in[8];
    const float* vb    = (const float*)d_in[9];

    float* out = (float*)d_out;
    // tuple (attention[B,DIM], align[B,T]) flattened in return order
    float *att_ptr, *align_ptr;
    if (out_size >= B_ * DIM_ + BT_) {
        att_ptr = out;
        align_ptr = out + B_ * DIM_;
    } else if (out_size == BT_) {          // align only
        float* p; cudaGetSymbolAddress((void**)&p, g_att_scratch);
        att_ptr = p; align_ptr = out;
    } else {                                // attention only
        float* p; cudaGetSymbolAddress((void**)&p, g_align_scratch);
        att_ptr = out; align_ptr = p;
    }

    k_reset<<<1, 1>>>();
    k_detect<<<64, 256>>>((const unsigned int*)mask);
    k_mconv<<<BT_ / 256, 256>>>(mask);
    k_qproj<<<B_, DIM_>>>(query, Wq);
    k_conv<<<dim3(T_ / 128, B_), 256>>>(pa, cw);
    k_score<<<dim3(8, B_), 256>>>(keys, Wloc, vw, vb);
    k_softmax<<<B_, 512>>>(align_ptr);
    k_context<<<dim3(4, B_), 256>>>(values, align_ptr);
    k_reduce<<<B_, DIM_>>>(att_ptr);
}

// round 10
// speedup vs baseline: 1.7281x; 1.7281x over previous
#include <cuda_runtime.h>
#include <cuda_bf16.h>
#include <cstdint>

#define B_   64
#define T_   4096
#define DIM_ 256
#define NF_  32
#define KS_  31
#define PAD_ 15
#define NEG_ (-1e30f)
#define BT_  (B_ * T_)

// ---------------- scratch (device globals; no allocations) ----------------
__device__ float g_q[B_ * DIM_];                     // 64 KB
__device__ __nv_bfloat16 g_Fh[(size_t)BT_ * NF_];    // 16 MB conv features (bf16)
__device__ float g_S[BT_];                           // raw masked scores
__device__ unsigned char g_mask[BT_];                // normalized mask
__device__ float g_partial[8 * B_ * DIM_];           // context partials
__device__ float g_align_scratch[BT_];
__device__ float g_att_scratch[B_ * DIM_];
__device__ int   g_det[2];

// ---------------- K0: mask dtype detection + normalization ----------------
__global__ void k_reset() { g_det[0] = 0; g_det[1] = 0; }

__global__ void k_detect(const unsigned int* __restrict__ mw) {
    int i = (blockIdx.x * 256 + threadIdx.x) * 4;
#pragma unroll
    for (int j = 0; j < 4; ++j) {
        unsigned v = mw[i + j];
        if (v == 0x3f800000u)      atomicOr(&g_det[1], 1);   // float 1.0
        else if (v > 1u)           atomicOr(&g_det[0], 1);   // packed bytes
    }
}

__global__ void k_mconv(const void* __restrict__ m) {
    int i = blockIdx.x * 256 + threadIdx.x;
    if (i >= BT_) return;
    int isf32 = g_det[1], isu8 = g_det[0];
    unsigned char r;
    if (isf32)      r = (((const float*)m)[i] != 0.0f);
    else if (isu8)  r = (((const unsigned char*)m)[i] != 0);
    else            r = (((const int*)m)[i] != 0);
    g_mask[i] = r;
}

// ---------------- K1: q = query @ Wq^T  (coalesced, warp-per-output) ------
__global__ void k_qproj(const float* __restrict__ query, const float* __restrict__ Wq) {
    __shared__ float qs[DIM_];
    const int b = blockIdx.x, tid = threadIdx.x;
    const int w = tid >> 5, lane = tid & 31;
    qs[tid] = query[b * DIM_ + tid];
    __syncthreads();
#pragma unroll 4
    for (int j = 0; j < 32; ++j) {
        const int d = w + j * 8;
        const float* wr = Wq + (size_t)d * DIM_;
        float a = 0.0f;
#pragma unroll
        for (int e = 0; e < 8; ++e)
            a = fmaf(wr[lane + 32 * e], qs[lane + 32 * e], a);
#pragma unroll
        for (int o = 16; o > 0; o >>= 1)
            a += __shfl_xor_sync(0xffffffffu, a, o);
        if (lane == 0) g_q[b * DIM_ + d] = a;
    }
}

// ---------------- K2: conv -> g_Fh (bf16). taps in regs, sliding window ---
__global__ void __launch_bounds__(256) k_conv(const float* __restrict__ pa,
                                              const float* __restrict__ cw) {
    __shared__ float pa_sh[160];             // 128 + 31 (one extra pad slot)
    __shared__ float cw_sh[NF_ * KS_];
    const int b = blockIdx.y, t0 = blockIdx.x * 128;
    const int tid = threadIdx.x, wid = tid >> 5, lane = tid & 31;
    for (int i = tid; i < 160; i += 256) {
        int t = t0 + i - PAD_;
        pa_sh[i] = (t >= 0 && t < T_) ? pa[b * T_ + t] : 0.0f;
    }
    for (int i = tid; i < NF_ * KS_; i += 256) cw_sh[i] = cw[i];
    __syncthreads();

    float cr[KS_];
#pragma unroll
    for (int k = 0; k < KS_; ++k) cr[k] = cw_sh[lane * KS_ + k];   // conflict-free (31 stride)
    float wv[KS_];
#pragma unroll
    for (int k = 0; k < KS_; ++k) wv[k] = pa_sh[wid * 16 + k];     // broadcast

    __nv_bfloat16* dst = g_Fh + ((size_t)(b * T_ + t0 + wid * 16)) * NF_ + lane;
#pragma unroll
    for (int i = 0; i < 16; ++i) {
        float a = 0.0f;
#pragma unroll
        for (int k = 0; k < KS_; ++k) a = fmaf(wv[k], cr[k], a);
        dst[(size_t)i * NF_] = __float2bfloat16(a);
#pragma unroll
        for (int k = 0; k < KS_ - 1; ++k) wv[k] = wv[k + 1];       // reg-renamed
        wv[KS_ - 1] = pa_sh[wid * 16 + i + KS_];                   // max idx 157 < 160
    }
}

// ---------------- K3: fused score kernel (bf16 tensor-core loc GEMM) ------
#define FP 40   // bf16 smem pitch: (row*20 + tig) mod 32 distinct -> conflict-free

__device__ __forceinline__ float score_term(float c, float kq, float v) {
    // v * tanh(c + kq),  tanh(x) = 1 - 2/(e^{2x}+1)
    float x = c + kq;
    float e = __expf(x + x);
    return v - __fdividef(v + v, e + 1.0f);
}

__global__ void __launch_bounds__(256)
k_score(const float* __restrict__ keys, const float* __restrict__ Wloc,
        const float* __restrict__ vw, const float* __restrict__ vb) {
    __shared__ __align__(16) __nv_bfloat16 F_sh[128 * FP];    // 10.0 KB
    __shared__ __align__(16) __nv_bfloat16 W_sh[DIM_ * FP];   // 20.0 KB
    __shared__ float q_sh[DIM_], v_sh[DIM_];

    const int b = blockIdx.y, t0 = blockIdx.x * 128;
    const int tid = threadIdx.x, w = tid >> 5, lane = tid & 31;
    const int g = lane >> 2, tg = lane & 3;

    // stage Wloc -> bf16 [d][f] (row-major == col-major k16n8 B operand)
    for (int idx = tid; idx < DIM_ * NF_; idx += 256)
        W_sh[(idx >> 5) * FP + (idx & 31)] = __float2bfloat16(Wloc[idx]);
    q_sh[tid] = g_q[b * DIM_ + tid];
    v_sh[tid] = vw[tid];
    // stage F tile (128 x 32 bf16) as u32
    {
        const uint32_t* src = (const uint32_t*)(g_Fh + (size_t)(b * T_ + t0) * NF_);
        uint32_t* dstF = (uint32_t*)F_sh;
        for (int idx = tid; idx < 128 * 16; idx += 256) {
            int row = idx >> 4, col = idx & 15;
            dstF[row * (FP / 2) + col] = src[idx];
        }
    }
    const float vb0 = vb[0];
    __syncthreads();

    // A fragments (m16k16, 2 k-steps) for this warp's 16 t-rows
    const __nv_bfloat16* Fb = F_sh + (w * 16) * FP;
    uint32_t a[2][4];
#pragma unroll
    for (int ks = 0; ks < 2; ++ks) {
        const int f0 = ks * 16 + 2 * tg;
        a[ks][0] = *(const uint32_t*)(Fb + g * FP + f0);
        a[ks][1] = *(const uint32_t*)(Fb + (g + 8) * FP + f0);
        a[ks][2] = *(const uint32_t*)(Fb + g * FP + f0 + 8);
        a[ks][3] = *(const uint32_t*)(Fb + (g + 8) * FP + f0 + 8);
    }

    const size_t row0 = (size_t)(b * T_ + t0 + w * 16 + g) * DIM_;
    const size_t row8 = row0 + 8 * DIM_;
    float sc0 = 0.0f, sc1 = 0.0f;

#pragma unroll 2
    for (int nt = 0; nt < 32; ++nt) {
        const int n0 = nt * 8;
        const int d  = n0 + 2 * tg;
        const __nv_bfloat16* Wb = W_sh + (n0 + g) * FP + 2 * tg;
        const uint32_t b00 = *(const uint32_t*)(Wb);
        const uint32_t b01 = *(const uint32_t*)(Wb + 8);
        const uint32_t b10 = *(const uint32_t*)(Wb + 16);
        const uint32_t b11 = *(const uint32_t*)(Wb + 24);
        // prefetch keys + per-d constants while MMA runs
        const float2 k0 = *(const float2*)(keys + row0 + d);
        const float2 k1 = *(const float2*)(keys + row8 + d);
        const float2 q2 = *(const float2*)&q_sh[d];
        const float2 v2 = *(const float2*)&v_sh[d];

        float c0 = 0.f, c1 = 0.f, c2 = 0.f, c3 = 0.f;
        asm volatile(
            "mma.sync.aligned.m16n8k16.row.col.f32.bf16.bf16.f32 "
            "{%0,%1,%2,%3}, {%4,%5,%6,%7}, {%8,%9}, {%0,%1,%2,%3};"
            : "+f"(c0), "+f"(c1), "+f"(c2), "+f"(c3)
            : "r"(a[0][0]), "r"(a[0][1]), "r"(a[0][2]), "r"(a[0][3]),
              "r"(b00), "r"(b01));
        asm volatile(
            "mma.sync.aligned.m16n8k16.row.col.f32.bf16.bf16.f32 "
            "{%0,%1,%2,%3}, {%4,%5,%6,%7}, {%8,%9}, {%0,%1,%2,%3};"
            : "+f"(c0), "+f"(c1), "+f"(c2), "+f"(c3)
            : "r"(a[1][0]), "r"(a[1][1]), "r"(a[1][2]), "r"(a[1][3]),
              "r"(b10), "r"(b11));

        sc0 += score_term(c0, k0.x + q2.x, v2.x) + score_term(c1, k0.y + q2.y, v2.y);
        sc1 += score_term(c2, k1.x + q2.x, v2.x) + score_term(c3, k1.y + q2.y, v2.y);
    }

    // reduce over the 4 lanes sharing a t-row (each covered d%8 in {2tg,2tg+1})
    sc0 += __shfl_xor_sync(0xffffffffu, sc0, 1);
    sc0 += __shfl_xor_sync(0xffffffffu, sc0, 2);
    sc1 += __shfl_xor_sync(0xffffffffu, sc1, 1);
    sc1 += __shfl_xor_sync(0xffffffffu, sc1, 2);
    if (tg == 0) {
        const int t = t0 + w * 16 + g;
        float s0 = sc0 + vb0; if (g_mask[b * T_ + t])     s0 = NEG_;
        float s1 = sc1 + vb0; if (g_mask[b * T_ + t + 8]) s1 = NEG_;
        g_S[b * T_ + t]     = s0;
        g_S[b * T_ + t + 8] = s1;
    }
}

// ---------------- K4: softmax per row ----------------
__global__ void k_softmax(float* __restrict__ align_out) {
    const int b = blockIdx.x, tid = threadIdx.x;   // 512 threads
    __shared__ float sha[16], shb[16];
    float v[8];
    float mx = -3.4e38f;
#pragma unroll
    for (int i = 0; i < 8; ++i) {
        v[i] = g_S[b * T_ + tid + i * 512];
        mx = fmaxf(mx, v[i]);
    }
#pragma unroll
    for (int o = 16; o > 0; o >>= 1) mx = fmaxf(mx, __shfl_xor_sync(0xffffffffu, mx, o));
    if ((tid & 31) == 0) sha[tid >> 5] = mx;
    __syncthreads();
    if (tid < 32) {
        float t = (tid < 16) ? sha[tid] : -3.4e38f;
#pragma unroll
        for (int o = 8; o > 0; o >>= 1) t = fmaxf(t, __shfl_xor_sync(0xffffffffu, t, o));
        if (tid == 0) sha[0] = t;
    }
    __syncthreads();
    mx = sha[0];
    float sum = 0.0f;
#pragma unroll
    for (int i = 0; i < 8; ++i) { v[i] = __expf(v[i] - mx); sum += v[i]; }
#pragma unroll
    for (int o = 16; o > 0; o >>= 1) sum += __shfl_xor_sync(0xffffffffu, sum, o);
    if ((tid & 31) == 0) shb[tid >> 5] = sum;
    __syncthreads();
    if (tid < 32) {
        float t = (tid < 16) ? shb[tid] : 0.0f;
#pragma unroll
        for (int o = 8; o > 0; o >>= 1) t += __shfl_xor_sync(0xffffffffu, t, o);
        if (tid == 0) shb[0] = t;
    }
    __syncthreads();
    const float inv = 1.0f / shb[0];
#pragma unroll
    for (int i = 0; i < 8; ++i)
        align_out[b * T_ + tid + i * 512] = v[i] * inv;
}

// ---------------- K5: context partials (8 splits) + K6: reduce ----------------
__global__ void __launch_bounds__(256) k_context(const float* __restrict__ values,
                                                 const float* __restrict__ align) {
    __shared__ float al[512];
    const int b = blockIdx.y, sp = blockIdx.x, tid = threadIdx.x;
    const int tbase = sp * 512;
    al[tid]       = align[b * T_ + tbase + tid];
    al[tid + 256] = align[b * T_ + tbase + tid + 256];
    __syncthreads();
    const float* vp = values + ((size_t)(b * T_ + tbase)) * DIM_ + tid;
    float acc = 0.0f;
#pragma unroll 16
    for (int t = 0; t < 512; ++t)
        acc = fmaf(al[t], vp[(size_t)t * DIM_], acc);
    g_partial[(sp * B_ + b) * DIM_ + tid] = acc;
}

__global__ void k_reduce(float* __restrict__ att_out) {
    const int b = blockIdx.x, d = threadIdx.x;
    float s = 0.0f;
#pragma unroll
    for (int sp = 0; sp < 8; ++sp) s += g_partial[(sp * B_ + b) * DIM_ + d];
    att_out[b * DIM_ + d] = s;
}

// ---------------- launch ----------------
extern "C" void kernel_launch(void* const* d_in, const int* in_sizes, int n_in,
                              void* d_out, int out_size) {
    const float* query  = (const float*)d_in[0];
    const float* keys   = (const float*)d_in[1];
    const float* values = (const float*)d_in[2];
    const float* pa     = (const float*)d_in[3];
    const void*  mask   = d_in[4];
    const float* Wq     = (const float*)d_in[5];
    const float* cw     = (const float*)d_in[6];
    const float* Wloc   = (const float*)d_in[7];
    const float* vw     = (const float*)d_in[8];
    const float* vb     = (const float*)d_in[9];

    float* out = (float*)d_out;
    float *att_ptr, *align_ptr;
    if (out_size >= B_ * DIM_ + BT_) {
        att_ptr = out;
        align_ptr = out + B_ * DIM_;
    } else if (out_size == BT_) {
        float* p; cudaGetSymbolAddress((void**)&p, g_att_scratch);
        att_ptr = p; align_ptr = out;
    } else {
        float* p; cudaGetSymbolAddress((void**)&p, g_align_scratch);
        att_ptr = out; align_ptr = p;
    }

    k_reset<<<1, 1>>>();
    k_detect<<<64, 256>>>((const unsigned int*)mask);
    k_mconv<<<BT_ / 256, 256>>>(mask);
    k_qproj<<<B_, 256>>>(query, Wq);
    k_conv<<<dim3(T_ / 128, B_), 256>>>(pa, cw);
    k_score<<<dim3(T_ / 128, B_), 256>>>(keys, Wloc, vw, vb);
    k_softmax<<<B_, 512>>>(align_ptr);
    k_context<<<dim3(8, B_), 256>>>(values, align_ptr);
    k_reduce<<<B_, DIM_>>>(att_ptr);
}